// round 11
// baseline (speedup 1.0000x reference)
#include <cuda_runtime.h>
#include <cuda_bf16.h>
#include <cstdint>

#define BB 8
#define CC 256
#define NN 2048

typedef __nv_bfloat16 bf16;

// ------------------------- scratch (device globals) -------------------------
__device__ bf16  g_xs [BB * NN * 2 * CC];   // x split  [b][n][hiC|loC]
__device__ bf16  g_Ws [3 * CC * 2 * CC];    // W split rows [q|v|k], [m][hiC|loC]
__device__ float g_bias[3 * CC];            // [q|v|k]
__device__ bf16  g_qs [BB * CC * 2 * NN];   // q split  [b*C+c][hiN|loN]
__device__ bf16  g_vs [BB * CC * 2 * NN];   // v split
__device__ bf16  g_ksT[BB * NN * 2 * CC];   // k^T split [b][n][hiC|loC]
__device__ float g_Mpart[48 * CC * CC];     // split-K partials (6 chunks x 8 b)
__device__ bf16  g_Ms [BB * CC * 2 * CC];   // M split  [b*C+c1][hiC2|loC2]
__device__ float g_xsum[BB * CC];
__device__ float g_spart[BB * CC];

// ------------------------- helpers -------------------------
__device__ __forceinline__ uint32_t smem_u32(const void* p) {
    uint32_t a;
    asm("{ .reg .u64 t; cvta.to.shared.u64 t, %1; cvt.u32.u64 %0, t; }" : "=r"(a) : "l"(p));
    return a;
}

__device__ __forceinline__ void cp_async16(uint32_t saddr, const void* gaddr) {
    asm volatile("cp.async.cg.shared.global [%0], [%1], 16;\n" :: "r"(saddr), "l"(gaddr));
}
__device__ __forceinline__ void cp_commit() {
    asm volatile("cp.async.commit_group;\n" ::: "memory");
}
template <int N>
__device__ __forceinline__ void cp_wait() {
    asm volatile("cp.async.wait_group %0;\n" :: "n"(N) : "memory");
}

__device__ __forceinline__ void ldmx4(unsigned* r, uint32_t addr) {
    asm volatile("ldmatrix.sync.aligned.m8n8.x4.shared.b16 {%0,%1,%2,%3}, [%4];\n"
                 : "=r"(r[0]), "=r"(r[1]), "=r"(r[2]), "=r"(r[3]) : "r"(addr));
}

__device__ __forceinline__ void mma16816(float* c, const unsigned* a,
                                         unsigned b0, unsigned b1) {
    asm volatile(
        "mma.sync.aligned.m16n8k16.row.col.f32.bf16.bf16.f32 "
        "{%0,%1,%2,%3},{%4,%5,%6,%7},{%8,%9},{%0,%1,%2,%3};\n"
        : "+f"(c[0]), "+f"(c[1]), "+f"(c[2]), "+f"(c[3])
        : "r"(a[0]), "r"(a[1]), "r"(a[2]), "r"(a[3]), "r"(b0), "r"(b1));
}

// split-bf16 K'' -> (ka, kb): t0: hi*hi, t1: Ahi*Blo, t2: Alo*Bhi
__device__ __forceinline__ void koffs(int kk, int K, int& ka, int& kb) {
    int term = kk / K;
    int kmod = kk - term * K;
    ka = (term == 2 ? K : 0) + kmod;
    kb = (term == 1 ? K : 0) + kmod;
}

__device__ __forceinline__ void split_store(bf16* row, int n, int lo_off,
                                            float v0, float v1)
{
    __nv_bfloat162 h, l;
    h.x = __float2bfloat16(v0);
    h.y = __float2bfloat16(v1);
    l.x = __float2bfloat16(v0 - __bfloat162float(h.x));
    l.y = __float2bfloat16(v1 - __bfloat162float(h.y));
    *reinterpret_cast<__nv_bfloat162*>(row + n)          = h;
    *reinterpret_cast<__nv_bfloat162*>(row + lo_off + n) = l;
}

// ------------------------- GEMM core (mma.sync) -------------------------
// BM=128, BN=128, BK=32 bf16. SMEM rows 80B (conflict-free ldmatrix: 16B-unit
// index r*5 mod 8 permutes 8 rows). 4-stage cp.async ring, one bar per iter.
// 8 warps: wm=w>>2, wn=w&3; warp tile 64x32; 4x4 m16n8k16 accumulator frags.
#define PITCH 80
#define TILEB (128 * PITCH)
#define NSTAGE 4
#define SMEMSZ (2 * NSTAGE * TILEB)   // 81920 B

template <typename EpiF>
__device__ __forceinline__ void gemm_core(
    const bf16* __restrict__ A, int ldA,
    const bf16* __restrict__ Bm, int ldB,
    int K, int kk0, int niter, int m0, int n0,
    uint32_t sbase, int tid, EpiF&& epi)
{
    const int lane = tid & 31;
    const int w    = tid >> 5;
    const int wm   = w >> 2;
    const int wn   = w & 3;
    const int g    = lane >> 2;
    const int t    = lane & 3;

    const int r0c = tid >> 2;                 // rows tid>>2 and +64
    const int c0c = (tid & 3) * 16;           // byte chunk within 64B row

    float acc[4][4][4];
#pragma unroll
    for (int i = 0; i < 4; i++)
#pragma unroll
        for (int j = 0; j < 4; j++)
#pragma unroll
            for (int q = 0; q < 4; q++) acc[i][j][q] = 0.f;

    const int lrow = lane & 15;
    const int lcol = (lane >> 4) * 16;

    auto issue = [&](int it) {
        int ka, kb; koffs(kk0 + it * 32, K, ka, kb);
        const bf16* pa = A  + ka + c0c / 2;
        const bf16* pb = Bm + kb + c0c / 2;
        const uint32_t da = sbase + (it % NSTAGE) * TILEB;
        const uint32_t db = sbase + NSTAGE * TILEB + (it % NSTAGE) * TILEB;
#pragma unroll
        for (int i = 0; i < 2; i++) {
            int r = r0c + i * 64;
            cp_async16(da + r * PITCH + c0c, pa + (size_t)(m0 + r) * ldA);
            cp_async16(db + r * PITCH + c0c, pb + (size_t)(n0 + r) * ldB);
        }
    };

    // prologue: 3 tiles in flight
    issue(0); cp_commit();
    issue(1); cp_commit();
    issue(2); cp_commit();

    for (int it = 0; it < niter; it++) {
        cp_wait<2>();          // tile `it` landed (one group per iter, uniform)
        __syncthreads();       // all reads of tile it-1 done -> stage (it+3)%4 free
        if (it + 3 < niter) issue(it + 3);
        cp_commit();           // always commit (empty tail groups keep count uniform)

        const uint32_t ca = sbase + (it % NSTAGE) * TILEB;
        const uint32_t cb = sbase + NSTAGE * TILEB + (it % NSTAGE) * TILEB;
#pragma unroll
        for (int s = 0; s < 2; s++) {
            const int cbyte = s * 32 + lcol;
            unsigned af[4][4];
#pragma unroll
            for (int mt = 0; mt < 4; mt++)
                ldmx4(af[mt], ca + (wm * 64 + mt * 16 + lrow) * PITCH + cbyte);
            unsigned bb[2][4];
#pragma unroll
            for (int p = 0; p < 2; p++)
                ldmx4(bb[p], cb + (wn * 32 + p * 16 + lrow) * PITCH + cbyte);
#pragma unroll
            for (int mt = 0; mt < 4; mt++)
#pragma unroll
                for (int nt = 0; nt < 4; nt++)
                    mma16816(acc[mt][nt], af[mt],
                             bb[nt >> 1][nt & 1], bb[nt >> 1][2 + (nt & 1)]);
        }
    }

#pragma unroll
    for (int mt = 0; mt < 4; mt++) {
#pragma unroll
        for (int nt = 0; nt < 4; nt++) {
            float* ac = acc[mt][nt];
            const int m = m0 + wm * 64 + mt * 16 + g;
            const int n = n0 + wn * 32 + nt * 8 + 2 * t;
#pragma unroll
            for (int h = 0; h < 2; h++)
                epi(m + h * 8, n, ac[2 * h + 0], ac[2 * h + 1]);
        }
    }
}

// ---- fused qv + kT GEMM (768 CTAs, 2:1 interleave) ----
// mode 0 (qv): A=Ws[0..512), B=xs_b, out split q/v.     512 CTAs
// mode 1 (kT): A=xs_b tokens, B=Ws[512..768), out ksT.  256 CTAs
__global__ __launch_bounds__(256, 2) void mm_qvk()
{
    extern __shared__ char dyns[];
    const uint32_t sbase = smem_u32(dyns);
    const int tid = threadIdx.x;
    const int bid = blockIdx.x;

    const int mode = ((bid % 3) == 2) ? 1 : 0;
    int b, m0, n0;
    const bf16 *A, *Bm;
    if (mode == 0) {
        const int idx = bid - bid / 3;          // 0..511
        b  = idx >> 6;
        const int rem = idx & 63;
        m0 = (rem >> 4) * 128;
        n0 = (rem & 15) * 128;
        A  = g_Ws;
        Bm = g_xs + (size_t)b * NN * 512;
    } else {
        const int idx = bid / 3;                // 0..255
        b  = idx >> 5;
        const int rem = idx & 31;
        m0 = (rem >> 1) * 128;
        n0 = (rem & 1) * 128;
        A  = g_xs + (size_t)b * NN * 512;
        Bm = g_Ws + (size_t)512 * 512;
    }

    gemm_core(A, 512, Bm, 512, CC, 0, 24, m0, n0, sbase, tid,
        [&](int mr, int n, float v0, float v1) {
            if (mode == 0) {
                const float bia = g_bias[mr];
                v0 += bia; v1 += bia;
                const int proj = mr >> 8;       // 0=q, 1=v (uniform per CTA)
                const int ml   = mr & 255;
                bf16* row = (proj ? g_vs : g_qs) + (size_t)(b * CC + ml) * 2 * NN;
                split_store(row, n, NN, v0, v1);
            } else {
                v0 += g_bias[512 + n];
                v1 += g_bias[512 + n + 1];
                bf16* row = g_ksT + (size_t)(b * NN + mr) * 512;
                split_store(row, n, CC, v0, v1);
            }
        });
}

// ---- vq GEMM: M = V Q^T, split-K 6 chunks -> Mpart ----
__global__ __launch_bounds__(256, 2) void mm_vq()
{
    extern __shared__ char dyns[];
    const uint32_t sbase = smem_u32(dyns);
    const int tid = threadIdx.x;
    const int bz  = blockIdx.z;
    const int b   = bz / 6;
    const int ch  = bz - 6 * b;
    const int m0  = blockIdx.y * 128;
    const int n0  = blockIdx.x * 128;

    const bf16* A  = g_vs + (size_t)b * CC * 2 * NN;
    const bf16* Bm = g_qs + (size_t)b * CC * 2 * NN;

    gemm_core(A, 2 * NN, Bm, 2 * NN, NN, ch * 1024, 32, m0, n0, sbase, tid,
        [&](int mr, int n, float v0, float v1) {
            *(float2*)&g_Mpart[((size_t)bz * CC + mr) * CC + n] = make_float2(v0, v1);
        });
}

// ---- out GEMM: out = (M K^T) * (1/S); 1/S computed per-CTA from g_spart ----
__global__ __launch_bounds__(256, 2) void mm_out(float* __restrict__ dout)
{
    extern __shared__ char dyns[];
    const uint32_t sbase = smem_u32(dyns);
    const int tid  = threadIdx.x;
    const int lane = tid & 31;
    const int b    = blockIdx.z;
    const int m0   = blockIdx.y * 128;
    const int n0   = blockIdx.x * 128;

    // per-CTA deterministic S reduction (identical in every CTA)
    __shared__ double sred[8];
    __shared__ float s_inv;
    double acc = 0.0;
    for (int i = tid; i < BB * CC; i += 256) acc += (double)g_spart[i];
#pragma unroll
    for (int off = 16; off > 0; off >>= 1)
        acc += __shfl_down_sync(0xFFFFFFFFu, acc, off);
    if (lane == 0) sred[tid >> 5] = acc;
    __syncthreads();
    if (tid == 0) {
        double s = 0.0;
#pragma unroll
        for (int i = 0; i < 8; i++) s += sred[i];
        s_inv = (float)(1.0 / s);
    }
    __syncthreads();
    const float inv = s_inv;

    const bf16* A  = g_Ms  + (size_t)b * CC * 512;
    const bf16* Bm = g_ksT + (size_t)b * NN * 512;

    gemm_core(A, 512, Bm, 512, CC, 0, 24, m0, n0, sbase, tid,
        [&](int mr, int n, float v0, float v1) {
            *(float2*)&dout[(size_t)(b * CC + mr) * NN + n] =
                make_float2(v0 * inv, v1 * inv);
        });
}

// ------------------------- prep / reduction kernels -------------------------

// W rows reordered [q|v|k], split to bf16 hi/lo; bias same order.
// Blocks 0..BB-1 also zero g_xsum (runs BEFORE transpose_split).
__global__ void wprep_kernel(const float* __restrict__ Wq, const float* __restrict__ bq,
                             const float* __restrict__ Wk, const float* __restrict__ bk,
                             const float* __restrict__ Wv, const float* __restrict__ bv)
{
    const int m = blockIdx.x;       // 0..767
    const int c = threadIdx.x;      // 0..255
    if (m < BB) g_xsum[m * CC + c] = 0.f;
    const float* Wsrc = (m < CC) ? Wq : (m < 2 * CC) ? Wv : Wk;
    const int ml = m & (CC - 1);
    const float v = Wsrc[ml * CC + c];
    const bf16 hi = __float2bfloat16(v);
    g_Ws[(size_t)m * 512 + c]       = hi;
    g_Ws[(size_t)m * 512 + CC + c]  = __float2bfloat16(v - __bfloat162float(hi));
    if (c == 0) g_bias[m] = (m < CC) ? bq[ml] : (m < 2 * CC) ? bv[ml] : bk[ml];
}

// x [b][C][N] fp32 -> g_xs [b][n][hiC|loC]; also accumulate xsum[b][c]
__global__ void transpose_split_kernel(const float* __restrict__ x)
{
    __shared__ float tile[32][33];
    const int b  = blockIdx.z;
    const int c0 = blockIdx.y * 32;
    const int n0 = blockIdx.x * 32;
    const float* S = x + (size_t)b * CC * NN;
    bf16* D = g_xs + (size_t)b * NN * 2 * CC;

#pragma unroll
    for (int i = 0; i < 4; i++)
        tile[threadIdx.y + i * 8][threadIdx.x] =
            S[(size_t)(c0 + threadIdx.y + i * 8) * NN + n0 + threadIdx.x];
    __syncthreads();

    if (threadIdx.y == 0) {
        float s = 0.f;
#pragma unroll
        for (int i = 0; i < 32; i++) s += tile[threadIdx.x][i];
        atomicAdd(&g_xsum[b * CC + c0 + threadIdx.x], s);
    }
#pragma unroll
    for (int i = 0; i < 4; i++) {
        const int n = n0 + threadIdx.y + i * 8;
        const int c = c0 + threadIdx.x;
        const float v = tile[threadIdx.x][threadIdx.y + i * 8];
        const bf16 hi = __float2bfloat16(v);
        D[(size_t)n * 2 * CC + c]      = hi;
        D[(size_t)n * 2 * CC + CC + c] = __float2bfloat16(v - __bfloat162float(hi));
    }
}

// Fused: blocks [0,2048): reduce 6 split-K chunks -> M split bf16.
//        blocks [2048,2304): spart[b,c] = (Wq[c]·xs_b + N·bq)·(Wk[c]·xs_b + N·bk)
__global__ __launch_bounds__(256) void mreduce_spartial_kernel(
    const float* __restrict__ Wq, const float* __restrict__ bq,
    const float* __restrict__ Wk, const float* __restrict__ bk)
{
    const int bid = blockIdx.x;
    if (bid < 2048) {
        const int b  = bid >> 8;
        const int c1 = bid & 255;
        const int c2 = threadIdx.x;
        float s = 0.f;
#pragma unroll
        for (int ch = 0; ch < 6; ch++)
            s += g_Mpart[((size_t)(b * 6 + ch) * CC + c1) * CC + c2];
        const bf16 hi = __float2bfloat16(s);
        g_Ms[(size_t)(b * CC + c1) * 512 + c2]      = hi;
        g_Ms[(size_t)(b * CC + c1) * 512 + CC + c2] = __float2bfloat16(s - __bfloat162float(hi));
    } else {
        __shared__ float xs[CC];
        const int idx  = bid - 2048;            // 0..255
        const int b    = idx >> 5;
        const int tid  = threadIdx.x;
        const int lane = tid & 31;
        const int w    = tid >> 5;
        const int c    = (idx & 31) * 8 + w;

        xs[tid] = g_xsum[b * CC + tid];
        __syncthreads();

        float qd = 0.f, kd = 0.f;
#pragma unroll
        for (int j = lane; j < CC; j += 32) {
            const float xv = xs[j];
            qd += Wq[c * CC + j] * xv;
            kd += Wk[c * CC + j] * xv;
        }
#pragma unroll
        for (int off = 16; off > 0; off >>= 1) {
            qd += __shfl_down_sync(0xFFFFFFFFu, qd, off);
            kd += __shfl_down_sync(0xFFFFFFFFu, kd, off);
        }
        if (lane == 0) {
            qd += (float)NN * bq[c];
            kd += (float)NN * bk[c];
            g_spart[b * CC + c] = qd * kd;
        }
    }
}

// ------------------------- launch -------------------------
extern "C" void kernel_launch(void* const* d_in, const int* in_sizes, int n_in,
                              void* d_out, int out_size)
{
    const float* x  = (const float*)d_in[0];
    const float* Wq = (const float*)d_in[1];
    const float* bq = (const float*)d_in[2];
    const float* Wk = (const float*)d_in[3];
    const float* bk = (const float*)d_in[4];
    const float* Wv = (const float*)d_in[5];
    const float* bv = (const float*)d_in[6];
    float* out = (float*)d_out;

    cudaFuncSetAttribute(mm_qvk, cudaFuncAttributeMaxDynamicSharedMemorySize, SMEMSZ);
    cudaFuncSetAttribute(mm_vq,  cudaFuncAttributeMaxDynamicSharedMemorySize, SMEMSZ);
    cudaFuncSetAttribute(mm_out, cudaFuncAttributeMaxDynamicSharedMemorySize, SMEMSZ);

    wprep_kernel<<<3 * CC, 256>>>(Wq, bq, Wk, bk, Wv, bv);  // also zeroes xsum
    transpose_split_kernel<<<dim3(NN / 32, CC / 32, BB), dim3(32, 8)>>>(x);

    // q|v projections + k^T, fused and interleaved (768 CTAs)
    mm_qvk<<<768, 256, SMEMSZ>>>();
    // M = V Q^T, split-K 6 chunks
    mm_vq<<<dim3(2, 2, BB * 6), 256, SMEMSZ>>>();
    // reduce M partials + compute S partials (independent halves of one launch)
    mreduce_spartial_kernel<<<2048 + 256, 256>>>(Wq, bq, Wk, bk);
    // out = (M K^T) / S   (each CTA derives 1/S deterministically)
    mm_out<<<dim3(16, 2, BB), 256, SMEMSZ>>>(out);
}

// round 12
// speedup vs baseline: 1.1091x; 1.1091x over previous
#include <cuda_runtime.h>
#include <cuda_bf16.h>
#include <cstdint>

#define BB 8
#define CC 256
#define NN 2048

typedef __nv_bfloat16 bf16;

// ------------------------- scratch (device globals) -------------------------
__device__ bf16  g_xs [BB * NN * 2 * CC];   // x split  [b][n][hiC|loC]
__device__ bf16  g_Ws [3 * CC * 2 * CC];    // W split rows [q|v|k], [m][hiC|loC]
__device__ float g_bias[3 * CC];            // [q|v|k]
__device__ bf16  g_qs [BB * CC * 2 * NN];   // q split  [b*C+c][hiN|loN]
__device__ bf16  g_vs [BB * CC * 2 * NN];   // v split
__device__ bf16  g_ksT[BB * NN * 2 * CC];   // k^T split [b][n][hiC|loC]
__device__ float g_Mpart[96 * CC * CC];     // split-K partials (12 chunks x 8 b)
__device__ bf16  g_Ms [BB * CC * 2 * CC];   // M split  [b*C+c1][hiC2|loC2]
__device__ float g_xsum[BB * CC];
__device__ float g_spart[BB * CC];

// ------------------------- helpers -------------------------
__device__ __forceinline__ uint32_t smem_u32(const void* p) {
    uint32_t a;
    asm("{ .reg .u64 t; cvta.to.shared.u64 t, %1; cvt.u32.u64 %0, t; }" : "=r"(a) : "l"(p));
    return a;
}

__device__ __forceinline__ void cp_async16(uint32_t saddr, const void* gaddr) {
    asm volatile("cp.async.cg.shared.global [%0], [%1], 16;\n" :: "r"(saddr), "l"(gaddr));
}
__device__ __forceinline__ void cp_commit() {
    asm volatile("cp.async.commit_group;\n" ::: "memory");
}
template <int N>
__device__ __forceinline__ void cp_wait() {
    asm volatile("cp.async.wait_group %0;\n" :: "n"(N) : "memory");
}

__device__ __forceinline__ void ldmx4(unsigned* r, uint32_t addr) {
    asm volatile("ldmatrix.sync.aligned.m8n8.x4.shared.b16 {%0,%1,%2,%3}, [%4];\n"
                 : "=r"(r[0]), "=r"(r[1]), "=r"(r[2]), "=r"(r[3]) : "r"(addr));
}

__device__ __forceinline__ void mma16816(float* c, const unsigned* a,
                                         unsigned b0, unsigned b1) {
    asm volatile(
        "mma.sync.aligned.m16n8k16.row.col.f32.bf16.bf16.f32 "
        "{%0,%1,%2,%3},{%4,%5,%6,%7},{%8,%9},{%0,%1,%2,%3};\n"
        : "+f"(c[0]), "+f"(c[1]), "+f"(c[2]), "+f"(c[3])
        : "r"(a[0]), "r"(a[1]), "r"(a[2]), "r"(a[3]), "r"(b0), "r"(b1));
}

// split-bf16 K'' -> (ka, kb): t0: hi*hi, t1: Ahi*Blo, t2: Alo*Bhi
__device__ __forceinline__ void koffs(int kk, int K, int& ka, int& kb) {
    int term = kk / K;
    int kmod = kk - term * K;
    ka = (term == 2 ? K : 0) + kmod;
    kb = (term == 1 ? K : 0) + kmod;
}

__device__ __forceinline__ void split_store(bf16* row, int n, int lo_off,
                                            float v0, float v1)
{
    __nv_bfloat162 h, l;
    h.x = __float2bfloat16(v0);
    h.y = __float2bfloat16(v1);
    l.x = __float2bfloat16(v0 - __bfloat162float(h.x));
    l.y = __float2bfloat16(v1 - __bfloat162float(h.y));
    *reinterpret_cast<__nv_bfloat162*>(row + n)          = h;
    *reinterpret_cast<__nv_bfloat162*>(row + lo_off + n) = l;
}

// ------------------------- mma.sync GEMM -------------------------
// BM=128, BN=128, BK=32 bf16. SMEM rows 80B (conflict-free ldmatrix: 16B-unit
// index r*5 mod 8 permutes 8 rows). 3-stage cp.async ring, one bar per iter.
// 8 warps: wm=w>>2, wn=w&3; warp tile 64x32; 4x4 m16n8k16 accumulator frags.
// EPI 0: qv  A=Ws[0..512)      B=xs_b          K'=768   -> split q/v
// EPI 1: kT  A=xs_b (tokens)   B=Ws[512..768)  K'=768   -> ksT split
// EPI 2: vq  A=vs_b  B=qs_b    K'=6144 (12 chunks x512) -> Mpart fp32
// EPI 3: out A=Ms_b  B=ksT_b   K'=768, scaled by 1/S    -> dout
#define PITCH 80
#define TILEB (128 * PITCH)
#define SMEMSZ (6 * TILEB)        // 3 stages x (A + B) = 61440 B

template <int EPI>
__global__ __launch_bounds__(256, 2) void mm_gemm(float* __restrict__ dout)
{
    extern __shared__ char dyns[];
    const uint32_t sbase = smem_u32(dyns);

    const int tid  = threadIdx.x;
    const int lane = tid & 31;
    const int w    = tid >> 5;
    const int wm   = w >> 2;
    const int wn   = w & 3;
    const int g    = lane >> 2;
    const int t    = lane & 3;

    const bf16 *A, *Bm;
    int ldA, ldB, K, kk0, niter, b, m0, n0, bz = blockIdx.z;
    if (EPI == 0) {
        b = bz; A = g_Ws; ldA = 512;
        Bm = g_xs + (size_t)b * NN * 512; ldB = 512;
        K = CC; kk0 = 0; niter = 24;
        m0 = blockIdx.y * 128; n0 = blockIdx.x * 128;
    } else if (EPI == 1) {
        b = bz; A = g_xs + (size_t)b * NN * 512; ldA = 512;
        Bm = g_Ws + (size_t)512 * 512; ldB = 512;
        K = CC; kk0 = 0; niter = 24;
        m0 = blockIdx.y * 128; n0 = blockIdx.x * 128;
    } else if (EPI == 2) {
        b = bz / 12; int ch = bz - 12 * b;
        A  = g_vs + (size_t)b * CC * 2 * NN; ldA = 2 * NN;
        Bm = g_qs + (size_t)b * CC * 2 * NN; ldB = 2 * NN;
        K = NN; kk0 = ch * 512; niter = 16;
        m0 = blockIdx.y * 128; n0 = blockIdx.x * 128;
    } else {
        b = bz; A = g_Ms + (size_t)b * CC * 512; ldA = 512;
        Bm = g_ksT + (size_t)b * NN * 512; ldB = 512;
        K = CC; kk0 = 0; niter = 24;
        m0 = blockIdx.y * 128; n0 = blockIdx.x * 128;
    }

    // EPI3: per-CTA deterministic 1/S from g_spart (identical in every CTA).
    // Uses the dynamic smem briefly BEFORE the pipeline prologue touches it.
    float inv = 1.f;
    if (EPI == 3) {
        double acc = 0.0;
        for (int i = tid; i < BB * CC; i += 256) acc += (double)g_spart[i];
#pragma unroll
        for (int off = 16; off > 0; off >>= 1)
            acc += __shfl_down_sync(0xFFFFFFFFu, acc, off);
        double* red = (double*)dyns;
        if (lane == 0) red[w] = acc;
        __syncthreads();
        double s = 0.0;
#pragma unroll
        for (int i = 0; i < 8; i++) s += red[i];
        inv = (float)(1.0 / s);
        __syncthreads();
    }

    // cp.async mapping: 512 x 16B chunks per tile, 2 per thread per operand
    const int r0c = tid >> 2;                 // rows tid>>2 and +64
    const int c0c = (tid & 3) * 16;           // byte chunk within 64B row

    float acc[4][4][4];
#pragma unroll
    for (int i = 0; i < 4; i++)
#pragma unroll
        for (int j = 0; j < 4; j++)
#pragma unroll
            for (int q = 0; q < 4; q++) acc[i][j][q] = 0.f;

    // ldmatrix per-thread offsets
    const int lrow = lane & 15;
    const int lcol = (lane >> 4) * 16;

    // issue loads of K-tile `it` into stage it%3
    auto issue = [&](int it) {
        int ka, kb; koffs(kk0 + it * 32, K, ka, kb);
        const bf16* pa = A  + ka + c0c / 2;
        const bf16* pb = Bm + kb + c0c / 2;
        const uint32_t da = sbase + (it % 3) * TILEB;
        const uint32_t db = sbase + 3 * TILEB + (it % 3) * TILEB;
#pragma unroll
        for (int i = 0; i < 2; i++) {
            int r = r0c + i * 64;
            cp_async16(da + r * PITCH + c0c, pa + (size_t)(m0 + r) * ldA);
            cp_async16(db + r * PITCH + c0c, pb + (size_t)(n0 + r) * ldB);
        }
    };

    // prologue: tiles 0 and 1 in flight
    issue(0); cp_commit();
    issue(1); cp_commit();

    for (int it = 0; it < niter; it++) {
        cp_wait<1>();          // tile `it` landed (groups: one per iter, uniform)
        __syncthreads();       // everyone done reading tile it-1 -> stage (it+2)%3 free
        if (it + 2 < niter) issue(it + 2);
        cp_commit();           // always commit (empty tail groups keep count uniform)

        const uint32_t ca = sbase + (it % 3) * TILEB;
        const uint32_t cb = sbase + 3 * TILEB + (it % 3) * TILEB;
#pragma unroll
        for (int s = 0; s < 2; s++) {
            const int cbyte = s * 32 + lcol;
            unsigned af[4][4];
#pragma unroll
            for (int mt = 0; mt < 4; mt++)
                ldmx4(af[mt], ca + (wm * 64 + mt * 16 + lrow) * PITCH + cbyte);
            unsigned bb[2][4];
#pragma unroll
            for (int p = 0; p < 2; p++)
                ldmx4(bb[p], cb + (wn * 32 + p * 16 + lrow) * PITCH + cbyte);
#pragma unroll
            for (int mt = 0; mt < 4; mt++)
#pragma unroll
                for (int nt = 0; nt < 4; nt++)
                    mma16816(acc[mt][nt], af[mt],
                             bb[nt >> 1][nt & 1], bb[nt >> 1][2 + (nt & 1)]);
        }
    }

    // ---- epilogue ----
#pragma unroll
    for (int mt = 0; mt < 4; mt++) {
#pragma unroll
        for (int nt = 0; nt < 4; nt++) {
            float* ac = acc[mt][nt];
            const int m = m0 + wm * 64 + mt * 16 + g;
            const int n = n0 + wn * 32 + nt * 8 + 2 * t;
#pragma unroll
            for (int h = 0; h < 2; h++) {
                const int mr = m + h * 8;
                float v0 = ac[2 * h + 0], v1 = ac[2 * h + 1];
                if (EPI == 0) {
                    const float bia = g_bias[mr];
                    v0 += bia; v1 += bia;
                    const int proj = mr >> 8;        // 0=q, 1=v (uniform per CTA)
                    const int ml   = mr & 255;
                    bf16* row = (proj ? g_vs : g_qs) + (size_t)(b * CC + ml) * 2 * NN;
                    split_store(row, n, NN, v0, v1);
                } else if (EPI == 1) {
                    v0 += g_bias[512 + n];
                    v1 += g_bias[512 + n + 1];
                    bf16* row = g_ksT + (size_t)(b * NN + mr) * 512;
                    split_store(row, n, CC, v0, v1);
                } else if (EPI == 2) {
                    *(float2*)&g_Mpart[((size_t)bz * CC + mr) * CC + n] =
                        make_float2(v0, v1);
                } else {
                    *(float2*)&dout[(size_t)(b * CC + mr) * NN + n] =
                        make_float2(v0 * inv, v1 * inv);
                }
            }
        }
    }
}

// ------------------------- prep / reduction kernels -------------------------

// W rows reordered [q|v|k], split to bf16 hi/lo; bias same order.
// Blocks 0..BB-1 also zero g_xsum (runs BEFORE transpose_split).
__global__ void wprep_kernel(const float* __restrict__ Wq, const float* __restrict__ bq,
                             const float* __restrict__ Wk, const float* __restrict__ bk,
                             const float* __restrict__ Wv, const float* __restrict__ bv)
{
    const int m = blockIdx.x;       // 0..767
    const int c = threadIdx.x;      // 0..255
    if (m < BB) g_xsum[m * CC + c] = 0.f;
    const float* Wsrc = (m < CC) ? Wq : (m < 2 * CC) ? Wv : Wk;
    const int ml = m & (CC - 1);
    const float v = Wsrc[ml * CC + c];
    const bf16 hi = __float2bfloat16(v);
    g_Ws[(size_t)m * 512 + c]       = hi;
    g_Ws[(size_t)m * 512 + CC + c]  = __float2bfloat16(v - __bfloat162float(hi));
    if (c == 0) g_bias[m] = (m < CC) ? bq[ml] : (m < 2 * CC) ? bv[ml] : bk[ml];
}

// x [b][C][N] fp32 -> g_xs [b][n][hiC|loC]; also accumulate xsum[b][c]
__global__ void transpose_split_kernel(const float* __restrict__ x)
{
    __shared__ float tile[32][33];
    const int b  = blockIdx.z;
    const int c0 = blockIdx.y * 32;
    const int n0 = blockIdx.x * 32;
    const float* S = x + (size_t)b * CC * NN;
    bf16* D = g_xs + (size_t)b * NN * 2 * CC;

#pragma unroll
    for (int i = 0; i < 4; i++)
        tile[threadIdx.y + i * 8][threadIdx.x] =
            S[(size_t)(c0 + threadIdx.y + i * 8) * NN + n0 + threadIdx.x];
    __syncthreads();

    if (threadIdx.y == 0) {
        float s = 0.f;
#pragma unroll
        for (int i = 0; i < 32; i++) s += tile[threadIdx.x][i];
        atomicAdd(&g_xsum[b * CC + c0 + threadIdx.x], s);
    }
#pragma unroll
    for (int i = 0; i < 4; i++) {
        const int n = n0 + threadIdx.y + i * 8;
        const int c = c0 + threadIdx.x;
        const float v = tile[threadIdx.x][threadIdx.y + i * 8];
        const bf16 hi = __float2bfloat16(v);
        D[(size_t)n * 2 * CC + c]      = hi;
        D[(size_t)n * 2 * CC + CC + c] = __float2bfloat16(v - __bfloat162float(hi));
    }
}

// Fused: blocks [0,2048): reduce 12 split-K chunks -> M split bf16.
//        blocks [2048,2304): spart[b,c] = (Wq[c]·xs_b + N·bq)·(Wk[c]·xs_b + N·bk)
__global__ __launch_bounds__(256) void mreduce_spartial_kernel(
    const float* __restrict__ Wq, const float* __restrict__ bq,
    const float* __restrict__ Wk, const float* __restrict__ bk)
{
    const int bid = blockIdx.x;
    if (bid < 2048) {
        const int b  = bid >> 8;
        const int c1 = bid & 255;
        const int c2 = threadIdx.x;
        float s = 0.f;
#pragma unroll
        for (int ch = 0; ch < 12; ch++)
            s += g_Mpart[((size_t)(b * 12 + ch) * CC + c1) * CC + c2];
        const bf16 hi = __float2bfloat16(s);
        g_Ms[(size_t)(b * CC + c1) * 512 + c2]      = hi;
        g_Ms[(size_t)(b * CC + c1) * 512 + CC + c2] = __float2bfloat16(s - __bfloat162float(hi));
    } else {
        __shared__ float xs[CC];
        const int idx  = bid - 2048;            // 0..255
        const int b    = idx >> 5;
        const int tid  = threadIdx.x;
        const int lane = tid & 31;
        const int w    = tid >> 5;
        const int c    = (idx & 31) * 8 + w;

        xs[tid] = g_xsum[b * CC + tid];
        __syncthreads();

        float qd = 0.f, kd = 0.f;
#pragma unroll
        for (int j = lane; j < CC; j += 32) {
            const float xv = xs[j];
            qd += Wq[c * CC + j] * xv;
            kd += Wk[c * CC + j] * xv;
        }
#pragma unroll
        for (int off = 16; off > 0; off >>= 1) {
            qd += __shfl_down_sync(0xFFFFFFFFu, qd, off);
            kd += __shfl_down_sync(0xFFFFFFFFu, kd, off);
        }
        if (lane == 0) {
            qd += (float)NN * bq[c];
            kd += (float)NN * bk[c];
            g_spart[b * CC + c] = qd * kd;
        }
    }
}

// ------------------------- launch -------------------------
extern "C" void kernel_launch(void* const* d_in, const int* in_sizes, int n_in,
                              void* d_out, int out_size)
{
    const float* x  = (const float*)d_in[0];
    const float* Wq = (const float*)d_in[1];
    const float* bq = (const float*)d_in[2];
    const float* Wk = (const float*)d_in[3];
    const float* bk = (const float*)d_in[4];
    const float* Wv = (const float*)d_in[5];
    const float* bv = (const float*)d_in[6];
    float* out = (float*)d_out;

    cudaFuncSetAttribute(mm_gemm<0>, cudaFuncAttributeMaxDynamicSharedMemorySize, SMEMSZ);
    cudaFuncSetAttribute(mm_gemm<1>, cudaFuncAttributeMaxDynamicSharedMemorySize, SMEMSZ);
    cudaFuncSetAttribute(mm_gemm<2>, cudaFuncAttributeMaxDynamicSharedMemorySize, SMEMSZ);
    cudaFuncSetAttribute(mm_gemm<3>, cudaFuncAttributeMaxDynamicSharedMemorySize, SMEMSZ);

    wprep_kernel<<<3 * CC, 256>>>(Wq, bq, Wk, bk, Wv, bv);  // also zeroes xsum
    transpose_split_kernel<<<dim3(NN / 32, CC / 32, BB), dim3(32, 8)>>>(x);

    // q|v projections: M=512, N=2048 per b
    mm_gemm<0><<<dim3(16, 4, BB), 256, SMEMSZ>>>(nullptr);
    // k^T: M=2048 tokens, N=256 channels per b
    mm_gemm<1><<<dim3(2, 16, BB), 256, SMEMSZ>>>(nullptr);
    // M = V Q^T, split-K 12 chunks (384 CTAs)
    mm_gemm<2><<<dim3(2, 2, BB * 12), 256, SMEMSZ>>>(nullptr);
    // reduce M partials + compute S partials (independent halves of one launch)
    mreduce_spartial_kernel<<<2048 + 256, 256>>>(Wq, bq, Wk, bk);
    // out = (M K^T) / S   (each CTA derives 1/S deterministically)
    mm_gemm<3><<<dim3(16, 2, BB), 256, SMEMSZ>>>(out);
}

// round 13
// speedup vs baseline: 1.1277x; 1.0168x over previous
#include <cuda_runtime.h>
#include <cuda_bf16.h>
#include <cstdint>

#define BB 8
#define CC 256
#define NN 2048

typedef __nv_bfloat16 bf16;

// ------------------------- scratch (device globals) -------------------------
__device__ bf16  g_xs [BB * NN * 2 * CC];   // x split  [b][n][hiC|loC]
__device__ bf16  g_Ws [3 * CC * 2 * CC];    // W split rows [q|v|k], [m][hiC|loC]
__device__ float g_bias[3 * CC];            // [q|v|k]
__device__ bf16  g_qs [BB * CC * 2 * NN];   // q split  [b*C+c][hiN|loN]
__device__ bf16  g_vs [BB * CC * 2 * NN];   // v split
__device__ bf16  g_ksT[BB * NN * 2 * CC];   // k^T split [b][n][hiC|loC]
__device__ float g_Mpart[96 * CC * CC];     // split-K partials (12 chunks x 8 b)
__device__ bf16  g_Ms [BB * CC * 2 * CC];   // M split  [b*C+c1][hiC2|loC2]
__device__ float g_xsum[BB * CC];
__device__ float g_spart[BB * CC];

// ------------------------- helpers -------------------------
__device__ __forceinline__ uint32_t smem_u32(const void* p) {
    uint32_t a;
    asm("{ .reg .u64 t; cvta.to.shared.u64 t, %1; cvt.u32.u64 %0, t; }" : "=r"(a) : "l"(p));
    return a;
}

__device__ __forceinline__ void cp_async16(uint32_t saddr, const void* gaddr) {
    asm volatile("cp.async.cg.shared.global [%0], [%1], 16;\n" :: "r"(saddr), "l"(gaddr));
}
__device__ __forceinline__ void cp_commit() {
    asm volatile("cp.async.commit_group;\n" ::: "memory");
}
template <int N>
__device__ __forceinline__ void cp_wait() {
    asm volatile("cp.async.wait_group %0;\n" :: "n"(N) : "memory");
}

__device__ __forceinline__ void ldmx4(unsigned* r, uint32_t addr) {
    asm volatile("ldmatrix.sync.aligned.m8n8.x4.shared.b16 {%0,%1,%2,%3}, [%4];\n"
                 : "=r"(r[0]), "=r"(r[1]), "=r"(r[2]), "=r"(r[3]) : "r"(addr));
}

__device__ __forceinline__ void mma16816(float* c, const unsigned* a,
                                         unsigned b0, unsigned b1) {
    asm volatile(
        "mma.sync.aligned.m16n8k16.row.col.f32.bf16.bf16.f32 "
        "{%0,%1,%2,%3},{%4,%5,%6,%7},{%8,%9},{%0,%1,%2,%3};\n"
        : "+f"(c[0]), "+f"(c[1]), "+f"(c[2]), "+f"(c[3])
        : "r"(a[0]), "r"(a[1]), "r"(a[2]), "r"(a[3]), "r"(b0), "r"(b1));
}

// split-bf16 K'' -> (ka, kb): t0: hi*hi, t1: Ahi*Blo, t2: Alo*Bhi
__device__ __forceinline__ void koffs(int kk, int K, int& ka, int& kb) {
    int term = kk / K;
    int kmod = kk - term * K;
    ka = (term == 2 ? K : 0) + kmod;
    kb = (term == 1 ? K : 0) + kmod;
}

__device__ __forceinline__ void split_store(bf16* row, int n, int lo_off,
                                            float v0, float v1)
{
    __nv_bfloat162 h, l;
    h.x = __float2bfloat16(v0);
    h.y = __float2bfloat16(v1);
    l.x = __float2bfloat16(v0 - __bfloat162float(h.x));
    l.y = __float2bfloat16(v1 - __bfloat162float(h.y));
    *reinterpret_cast<__nv_bfloat162*>(row + n)          = h;
    *reinterpret_cast<__nv_bfloat162*>(row + lo_off + n) = l;
}

// ------------------------- mma.sync GEMM core -------------------------
// BM=128, BN=128, BK=32 bf16. SMEM rows 80B (conflict-free ldmatrix: 16B-unit
// index r*5 mod 8 permutes 8 rows). 3-stage cp.async ring, one bar per iter.
// 8 warps: wm=w>>2, wn=w&3; warp tile 64x32; 4x4 m16n8k16 accumulator frags.
#define PITCH 80
#define TILEB (128 * PITCH)
#define SMEMSZ (6 * TILEB)        // 3 stages x (A + B) = 61440 B

template <typename EpiF>
__device__ __forceinline__ void gemm_core(
    const bf16* __restrict__ A, int ldA,
    const bf16* __restrict__ Bm, int ldB,
    int K, int kk0, int niter, int m0, int n0,
    uint32_t sbase, int tid, EpiF&& epi)
{
    const int lane = tid & 31;
    const int w    = tid >> 5;
    const int wm   = w >> 2;
    const int wn   = w & 3;
    const int g    = lane >> 2;
    const int t    = lane & 3;

    const int r0c = tid >> 2;                 // rows tid>>2 and +64
    const int c0c = (tid & 3) * 16;           // byte chunk within 64B row

    float acc[4][4][4];
#pragma unroll
    for (int i = 0; i < 4; i++)
#pragma unroll
        for (int j = 0; j < 4; j++)
#pragma unroll
            for (int q = 0; q < 4; q++) acc[i][j][q] = 0.f;

    const int lrow = lane & 15;
    const int lcol = (lane >> 4) * 16;

    auto issue = [&](int it) {
        int ka, kb; koffs(kk0 + it * 32, K, ka, kb);
        const bf16* pa = A  + ka + c0c / 2;
        const bf16* pb = Bm + kb + c0c / 2;
        const uint32_t da = sbase + (it % 3) * TILEB;
        const uint32_t db = sbase + 3 * TILEB + (it % 3) * TILEB;
#pragma unroll
        for (int i = 0; i < 2; i++) {
            int r = r0c + i * 64;
            cp_async16(da + r * PITCH + c0c, pa + (size_t)(m0 + r) * ldA);
            cp_async16(db + r * PITCH + c0c, pb + (size_t)(n0 + r) * ldB);
        }
    };

    issue(0); cp_commit();
    issue(1); cp_commit();

    for (int it = 0; it < niter; it++) {
        cp_wait<1>();          // tile `it` landed (one group per iter, uniform)
        __syncthreads();       // reads of tile it-1 done -> stage (it+2)%3 free
        if (it + 2 < niter) issue(it + 2);
        cp_commit();           // empty tail groups keep the count uniform

        const uint32_t ca = sbase + (it % 3) * TILEB;
        const uint32_t cb = sbase + 3 * TILEB + (it % 3) * TILEB;
#pragma unroll
        for (int s = 0; s < 2; s++) {
            const int cbyte = s * 32 + lcol;
            unsigned af[4][4];
#pragma unroll
            for (int mt = 0; mt < 4; mt++)
                ldmx4(af[mt], ca + (wm * 64 + mt * 16 + lrow) * PITCH + cbyte);
            unsigned bb[2][4];
#pragma unroll
            for (int p = 0; p < 2; p++)
                ldmx4(bb[p], cb + (wn * 32 + p * 16 + lrow) * PITCH + cbyte);
#pragma unroll
            for (int mt = 0; mt < 4; mt++)
#pragma unroll
                for (int nt = 0; nt < 4; nt++)
                    mma16816(acc[mt][nt], af[mt],
                             bb[nt >> 1][nt & 1], bb[nt >> 1][2 + (nt & 1)]);
        }
    }

#pragma unroll
    for (int mt = 0; mt < 4; mt++) {
#pragma unroll
        for (int nt = 0; nt < 4; nt++) {
            float* ac = acc[mt][nt];
            const int m = m0 + wm * 64 + mt * 16 + g;
            const int n = n0 + wn * 32 + nt * 8 + 2 * t;
#pragma unroll
            for (int h = 0; h < 2; h++)
                epi(m + h * 8, n, ac[2 * h + 0], ac[2 * h + 1]);
        }
    }
}

// ---- qv GEMM: q|v projections (512 CTAs) ----
__global__ __launch_bounds__(256, 2) void mm_qv()
{
    extern __shared__ char dyns[];
    const uint32_t sbase = smem_u32(dyns);
    const int tid = threadIdx.x;
    const int b   = blockIdx.z;
    const int m0  = blockIdx.y * 128;
    const int n0  = blockIdx.x * 128;

    gemm_core(g_Ws, 512, g_xs + (size_t)b * NN * 512, 512, CC, 0, 24,
              m0, n0, sbase, tid,
        [&](int mr, int n, float v0, float v1) {
            const float bia = g_bias[mr];
            v0 += bia; v1 += bia;
            const int proj = mr >> 8;       // 0=q, 1=v (uniform per CTA)
            const int ml   = mr & 255;
            bf16* row = (proj ? g_vs : g_qs) + (size_t)(b * CC + ml) * 2 * NN;
            split_store(row, n, NN, v0, v1);
        });
}

// ---- fused kT + vq GEMM (640 CTAs, sequential ranges) ----
// bid [0,384):  vq  M = V Q^T, split-K 12 -> Mpart
// bid [384,640): kT  k^T = x^T Wk^T       -> ksT split
__global__ __launch_bounds__(256, 2) void mm_ktvq()
{
    extern __shared__ char dyns[];
    const uint32_t sbase = smem_u32(dyns);
    const int tid = threadIdx.x;
    const int bid = blockIdx.x;

    if (bid < 384) {
        const int bz = bid >> 2;            // 0..95 = b*12+ch
        const int b  = bz / 12;
        const int ch = bz - 12 * b;
        const int m0 = ((bid >> 1) & 1) * 128;
        const int n0 = (bid & 1) * 128;
        const bf16* A  = g_vs + (size_t)b * CC * 2 * NN;
        const bf16* Bm = g_qs + (size_t)b * CC * 2 * NN;
        gemm_core(A, 2 * NN, Bm, 2 * NN, NN, ch * 512, 16, m0, n0, sbase, tid,
            [&](int mr, int n, float v0, float v1) {
                *(float2*)&g_Mpart[((size_t)bz * CC + mr) * CC + n] =
                    make_float2(v0, v1);
            });
    } else {
        const int idx = bid - 384;          // 0..255
        const int b   = idx >> 5;
        const int rem = idx & 31;
        const int m0  = (rem >> 1) * 128;   // token tile
        const int n0  = (rem & 1) * 128;    // channel tile
        const bf16* A  = g_xs + (size_t)b * NN * 512;
        const bf16* Bm = g_Ws + (size_t)512 * 512;
        gemm_core(A, 512, Bm, 512, CC, 0, 24, m0, n0, sbase, tid,
            [&](int mr, int n, float v0, float v1) {
                v0 += g_bias[512 + n];
                v1 += g_bias[512 + n + 1];
                bf16* row = g_ksT + (size_t)(b * NN + mr) * 512;
                split_store(row, n, CC, v0, v1);
            });
    }
}

// ---- out GEMM: out = (M K^T) * (1/S); 1/S computed per-CTA from g_spart ----
__global__ __launch_bounds__(256, 2) void mm_out(float* __restrict__ dout)
{
    extern __shared__ char dyns[];
    const uint32_t sbase = smem_u32(dyns);
    const int tid  = threadIdx.x;
    const int lane = tid & 31;
    const int w    = tid >> 5;
    const int b    = blockIdx.z;
    const int m0   = blockIdx.y * 128;
    const int n0   = blockIdx.x * 128;

    // per-CTA deterministic 1/S (identical in every CTA); uses dyn smem
    // BEFORE the pipeline prologue touches it.
    float inv;
    {
        double acc = 0.0;
        for (int i = tid; i < BB * CC; i += 256) acc += (double)g_spart[i];
#pragma unroll
        for (int off = 16; off > 0; off >>= 1)
            acc += __shfl_down_sync(0xFFFFFFFFu, acc, off);
        double* red = (double*)dyns;
        if (lane == 0) red[w] = acc;
        __syncthreads();
        double s = 0.0;
#pragma unroll
        for (int i = 0; i < 8; i++) s += red[i];
        inv = (float)(1.0 / s);
        __syncthreads();
    }

    gemm_core(g_Ms + (size_t)b * CC * 512, 512,
              g_ksT + (size_t)b * NN * 512, 512, CC, 0, 24,
              m0, n0, sbase, tid,
        [&](int mr, int n, float v0, float v1) {
            *(float2*)&dout[(size_t)(b * CC + mr) * NN + n] =
                make_float2(v0 * inv, v1 * inv);
        });
}

// ------------------------- prep / reduction kernels -------------------------

// W rows reordered [q|v|k], split to bf16 hi/lo; bias same order.
// Blocks 0..BB-1 also zero g_xsum (runs BEFORE transpose_split).
__global__ void wprep_kernel(const float* __restrict__ Wq, const float* __restrict__ bq,
                             const float* __restrict__ Wk, const float* __restrict__ bk,
                             const float* __restrict__ Wv, const float* __restrict__ bv)
{
    const int m = blockIdx.x;       // 0..767
    const int c = threadIdx.x;      // 0..255
    if (m < BB) g_xsum[m * CC + c] = 0.f;
    const float* Wsrc = (m < CC) ? Wq : (m < 2 * CC) ? Wv : Wk;
    const int ml = m & (CC - 1);
    const float v = Wsrc[ml * CC + c];
    const bf16 hi = __float2bfloat16(v);
    g_Ws[(size_t)m * 512 + c]       = hi;
    g_Ws[(size_t)m * 512 + CC + c]  = __float2bfloat16(v - __bfloat162float(hi));
    if (c == 0) g_bias[m] = (m < CC) ? bq[ml] : (m < 2 * CC) ? bv[ml] : bk[ml];
}

// x [b][C][N] fp32 -> g_xs [b][n][hiC|loC]; also accumulate xsum[b][c]
__global__ void transpose_split_kernel(const float* __restrict__ x)
{
    __shared__ float tile[32][33];
    const int b  = blockIdx.z;
    const int c0 = blockIdx.y * 32;
    const int n0 = blockIdx.x * 32;
    const float* S = x + (size_t)b * CC * NN;
    bf16* D = g_xs + (size_t)b * NN * 2 * CC;

#pragma unroll
    for (int i = 0; i < 4; i++)
        tile[threadIdx.y + i * 8][threadIdx.x] =
            S[(size_t)(c0 + threadIdx.y + i * 8) * NN + n0 + threadIdx.x];
    __syncthreads();

    if (threadIdx.y == 0) {
        float s = 0.f;
#pragma unroll
        for (int i = 0; i < 32; i++) s += tile[threadIdx.x][i];
        atomicAdd(&g_xsum[b * CC + c0 + threadIdx.x], s);
    }
#pragma unroll
    for (int i = 0; i < 4; i++) {
        const int n = n0 + threadIdx.y + i * 8;
        const int c = c0 + threadIdx.x;
        const float v = tile[threadIdx.x][threadIdx.y + i * 8];
        const bf16 hi = __float2bfloat16(v);
        D[(size_t)n * 2 * CC + c]      = hi;
        D[(size_t)n * 2 * CC + CC + c] = __float2bfloat16(v - __bfloat162float(hi));
    }
}

// Fused: blocks [0,2048): reduce 12 split-K chunks -> M split bf16.
//        blocks [2048,2304): spart[b,c] = (Wq[c]·xs_b + N·bq)·(Wk[c]·xs_b + N·bk)
__global__ __launch_bounds__(256) void mreduce_spartial_kernel(
    const float* __restrict__ Wq, const float* __restrict__ bq,
    const float* __restrict__ Wk, const float* __restrict__ bk)
{
    const int bid = blockIdx.x;
    if (bid < 2048) {
        const int b  = bid >> 8;
        const int c1 = bid & 255;
        const int c2 = threadIdx.x;
        float s = 0.f;
#pragma unroll
        for (int ch = 0; ch < 12; ch++)
            s += g_Mpart[((size_t)(b * 12 + ch) * CC + c1) * CC + c2];
        const bf16 hi = __float2bfloat16(s);
        g_Ms[(size_t)(b * CC + c1) * 512 + c2]      = hi;
        g_Ms[(size_t)(b * CC + c1) * 512 + CC + c2] = __float2bfloat16(s - __bfloat162float(hi));
    } else {
        __shared__ float xs[CC];
        const int idx  = bid - 2048;            // 0..255
        const int b    = idx >> 5;
        const int tid  = threadIdx.x;
        const int lane = tid & 31;
        const int w    = tid >> 5;
        const int c    = (idx & 31) * 8 + w;

        xs[tid] = g_xsum[b * CC + tid];
        __syncthreads();

        float qd = 0.f, kd = 0.f;
#pragma unroll
        for (int j = lane; j < CC; j += 32) {
            const float xv = xs[j];
            qd += Wq[c * CC + j] * xv;
            kd += Wk[c * CC + j] * xv;
        }
#pragma unroll
        for (int off = 16; off > 0; off >>= 1) {
            qd += __shfl_down_sync(0xFFFFFFFFu, qd, off);
            kd += __shfl_down_sync(0xFFFFFFFFu, kd, off);
        }
        if (lane == 0) {
            qd += (float)NN * bq[c];
            kd += (float)NN * bk[c];
            g_spart[b * CC + c] = qd * kd;
        }
    }
}

// ------------------------- launch -------------------------
extern "C" void kernel_launch(void* const* d_in, const int* in_sizes, int n_in,
                              void* d_out, int out_size)
{
    const float* x  = (const float*)d_in[0];
    const float* Wq = (const float*)d_in[1];
    const float* bq = (const float*)d_in[2];
    const float* Wk = (const float*)d_in[3];
    const float* bk = (const float*)d_in[4];
    const float* Wv = (const float*)d_in[5];
    const float* bv = (const float*)d_in[6];
    float* out = (float*)d_out;

    cudaFuncSetAttribute(mm_qv,   cudaFuncAttributeMaxDynamicSharedMemorySize, SMEMSZ);
    cudaFuncSetAttribute(mm_ktvq, cudaFuncAttributeMaxDynamicSharedMemorySize, SMEMSZ);
    cudaFuncSetAttribute(mm_out,  cudaFuncAttributeMaxDynamicSharedMemorySize, SMEMSZ);

    wprep_kernel<<<3 * CC, 256>>>(Wq, bq, Wk, bk, Wv, bv);  // also zeroes xsum
    transpose_split_kernel<<<dim3(NN / 32, CC / 32, BB), dim3(32, 8)>>>(x);

    // q|v projections: M=512, N=2048 per b (512 CTAs)
    mm_qv<<<dim3(16, 4, BB), 256, SMEMSZ>>>();
    // fused: vq split-K 12 (384 CTAs) + k^T (256 CTAs) in one launch
    mm_ktvq<<<640, 256, SMEMSZ>>>();
    // reduce M partials + compute S partials (independent halves of one launch)
    mreduce_spartial_kernel<<<2048 + 256, 256>>>(Wq, bq, Wk, bk);
    // out = (M K^T) / S   (each CTA derives 1/S deterministically)
    mm_out<<<dim3(16, 2, BB), 256, SMEMSZ>>>(out);
}